// round 12
// baseline (speedup 1.0000x reference)
#include <cuda_runtime.h>

// S4/DPLR kernel materialization, H=256, N2=64, RANK=1, CH=1, L=2048.
// Single pass, one warp per head (lane holds states n=lane, n=lane+32 packed
// as f32x2), T=8 blocked rank-1 Woodbury recurrence, linear recombination,
// smem-transpose reductions. R11 design with the rowsum FIXED to read the
// full 64-float row (16x LDS.128, packed f2add tree): u64 scatter, sign-baked
// dup stores (murN/muiP/muiN/kap), LDS.128 update multipliers.

#define T 8
#define ROWP 68   // floats per 64-float padded row (272B; conflict-free LDS.128)

typedef unsigned long long u64;

__device__ __forceinline__ float wsum(float v) {
    #pragma unroll
    for (int o = 16; o; o >>= 1) v += __shfl_xor_sync(0xffffffffu, v, o);
    return v;
}
__device__ __forceinline__ u64 pk(float x, float y) {
    u64 r; asm("mov.b64 %0,{%1,%2};" : "=l"(r) : "f"(x), "f"(y)); return r;
}
__device__ __forceinline__ float2 up(u64 a) {
    float2 v; asm("mov.b64 {%0,%1},%2;" : "=f"(v.x), "=f"(v.y) : "l"(a)); return v;
}
__device__ __forceinline__ u64 f2fma(u64 a, u64 b, u64 c) {
    u64 d; asm("fma.rn.f32x2 %0,%1,%2,%3;" : "=l"(d) : "l"(a), "l"(b), "l"(c)); return d;
}
__device__ __forceinline__ u64 f2mul(u64 a, u64 b) {
    u64 d; asm("mul.rn.f32x2 %0,%1,%2;" : "=l"(d) : "l"(a), "l"(b)); return d;
}
__device__ __forceinline__ u64 f2add(u64 a, u64 b) {
    u64 d; asm("add.rn.f32x2 %0,%1,%2;" : "=l"(d) : "l"(a), "l"(b)); return d;
}

__global__ __launch_bounds__(64, 1) void ssm_dplr_kernel(
    const float* __restrict__ Ar, const float* __restrict__ Ai,
    const float* __restrict__ Br, const float* __restrict__ Bi,
    const float* __restrict__ Pr, const float* __restrict__ Pi,
    const float* __restrict__ Cr, const float* __restrict__ Ci,
    const float* __restrict__ logdt,
    float* __restrict__ out, int H, int L)
{
    // per-warp buffers (2 warps = 2 heads per CTA)
    __shared__ __align__(16) float s_part[2][24 * ROWP];   // 24 rows x 64 floats
    __shared__ __align__(16) ulonglong2 s_pair[2][8];      // (murN_i, muiP_i)
    __shared__ __align__(16) u64 s_kap[2][8];              // kap dup
    __shared__ __align__(16) u64 s_muiN[2][8];             // -mui dup

    const int wip = threadIdx.x >> 5;
    const int lane = threadIdx.x & 31;
    const int h = blockIdx.x * 2 + wip;
    if (h >= H) return;
    const int base = h * 64 + lane;

    const float dt  = expf(logdt[h]);
    const float del = 0.5f * dt;

    // ---- per-slot scalar setup ----
    float er[2], ei[2], qr[2], qi[2], ur_[2], ui_[2], c2r[2], c2i[2];
    float pr[2], pi[2], d_r[2], d_i[2];
    float mmr[2], mmi[2];

    float red4[4];
    red4[0] = red4[1] = red4[2] = red4[3] = 0.f;
    #pragma unroll
    for (int s = 0; s < 2; ++s) {
        const int n = base + 32 * s;
        const float lr = -Ar[n], li = -Ai[n];
        const float ar = 1.f + del * lr, ai = del * li;
        const float mr = 1.f - del * lr, mi = -del * li;
        const float idm = 1.f / (mr * mr + mi * mi);
        d_r[s] = mr * idm; d_i[s] = -mi * idm;
        pr[s] = Pr[n]; pi[s] = Pi[n];
        er[s] = d_r[s] * ar - d_i[s] * ai;  ei[s] = d_r[s] * ai + d_i[s] * ar;
        qr[s] = d_r[s] * pr[s] - d_i[s] * pi[s];
        qi[s] = d_r[s] * pi[s] + d_i[s] * pr[s];
        c2r[s] = 2.f * Cr[n]; c2i[s] = 2.f * Ci[n];
        const float pp = pr[s] * pr[s] + pi[s] * pi[s];
        red4[0] += d_r[s] * pp; red4[1] += d_i[s] * pp;
        const float zr = dt * Br[n], zi = dt * Bi[n];
        mmr[s] = d_r[s] * zr - d_i[s] * zi;
        mmi[s] = d_r[s] * zi + d_i[s] * zr;
        red4[2] += pr[s] * mmr[s] + pi[s] * mmi[s];
        red4[3] += pr[s] * mmi[s] - pi[s] * mmr[s];
    }
    #pragma unroll
    for (int o = 16; o; o >>= 1)
        #pragma unroll
        for (int k = 0; k < 4; ++k)
            red4[k] += __shfl_xor_sync(0xffffffffu, red4[k], o);

    const float wr0 = 1.f + del * red4[0], wi0 = del * red4[1];
    const float iw = 1.f / (wr0 * wr0 + wi0 * wi0);
    const float gar = del * wr0 * iw, gai = -del * wi0 * iw;
    const float dkr = del * red4[0], dki = del * red4[1];
    const float alr = del - (gar * dkr - gai * dki);
    const float ali = -(gar * dki + gai * dkr);

    #pragma unroll
    for (int s = 0; s < 2; ++s) {
        const float gr2 = pr[s] * er[s] + pi[s] * ei[s];
        const float gi2 = pr[s] * ei[s] - pi[s] * er[s];
        ur_[s] = alr * pr[s] + ali * pi[s] + gar * gr2 - gai * gi2;
        ui_[s] = -alr * pi[s] + ali * pr[s] + gar * gi2 + gai * gr2;
    }

    // initial state x = dB
    float xr0[2], xi0[2];
    {
        const float gtr = gar * red4[2] - gai * red4[3];
        const float gti = gar * red4[3] + gai * red4[2];
        #pragma unroll
        for (int s = 0; s < 2; ++s) {
            xr0[s] = mmr[s] - (gtr * qr[s] - gti * qi[s]);
            xi0[s] = mmi[s] - (gtr * qi[s] + gti * qr[s]);
        }
    }

    // powers m=0..T-1
    float qer[T][2], qei[T][2], uer[T][2], uei[T][2], cer[T][2], cei[T][2];
    float e8r[2], e8i[2];
    {
        float emr[2] = {1.f, 1.f}, emi[2] = {0.f, 0.f};
        #pragma unroll
        for (int m = 0; m < T; ++m) {
            #pragma unroll
            for (int s = 0; s < 2; ++s) {
                qer[m][s] = qr[s] * emr[s] - qi[s] * emi[s];
                qei[m][s] = qr[s] * emi[s] + qi[s] * emr[s];
                uer[m][s] = ur_[s] * emr[s] - ui_[s] * emi[s];
                uei[m][s] = ur_[s] * emi[s] + ui_[s] * emr[s];
                cer[m][s] = c2r[s] * emr[s] - c2i[s] * emi[s];
                cei[m][s] = c2r[s] * emi[s] + c2i[s] * emr[s];
                const float t2 = emr[s] * er[s] - emi[s] * ei[s];
                emi[s] = emr[s] * ei[s] + emi[s] * er[s];
                emr[s] = t2;
            }
        }
        e8r[0] = emr[0]; e8i[0] = emi[0]; e8r[1] = emr[1]; e8i[1] = emi[1];
    }

    // nu_m, eta_m for m=0..T-2
    float red[4 * (T - 1)];
    #pragma unroll
    for (int m = 0; m < T - 1; ++m) {
        float a = 0.f, b = 0.f, c = 0.f, d = 0.f;
        #pragma unroll
        for (int s = 0; s < 2; ++s) {
            a += ur_[s] * qer[m][s] - ui_[s] * qei[m][s];
            b += ur_[s] * qei[m][s] + ui_[s] * qer[m][s];
            c += c2r[s] * qer[m][s] - c2i[s] * qei[m][s];
            d += c2r[s] * qei[m][s] + c2i[s] * qer[m][s];
        }
        red[4 * m] = a; red[4 * m + 1] = b; red[4 * m + 2] = c; red[4 * m + 3] = d;
    }
    #pragma unroll
    for (int o = 16; o; o >>= 1)
        #pragma unroll
        for (int k = 0; k < 4 * (T - 1); ++k)
            red[k] += __shfl_xor_sync(0xffffffffu, red[k], o);

    // beta = (1 + z*nu)^{-1}
    float btr[T], bti[T];
    btr[0] = 1.f; bti[0] = 0.f;
    #pragma unroll
    for (int m = 1; m < T; ++m) {
        float a = 0.f, b = 0.f;
        #pragma unroll
        for (int j = 0; j < m; ++j) {
            const float nr = red[4 * (m - 1 - j)], ni = red[4 * (m - 1 - j) + 1];
            a -= nr * btr[j] - ni * bti[j];
            b -= nr * bti[j] + ni * btr[j];
        }
        btr[m] = a; bti[m] = b;
    }
    // w = eta (*) beta
    float wcr[T - 1], wci[T - 1];
    #pragma unroll
    for (int m = 0; m < T - 1; ++m) {
        float a = 0.f, b = 0.f;
        #pragma unroll
        for (int j = 0; j <= m; ++j) {
            const float er2 = red[4 * j + 2], ei2 = red[4 * j + 3];
            a += er2 * btr[m - j] - ei2 * bti[m - j];
            b += er2 * bti[m - j] + ei2 * btr[m - j];
        }
        wcr[m] = a; wci[m] = b;
    }

    // R_i = sum_{j>=i} beta_{j-i} E^{T-1-j} q  (positive, packed)
    u64 RrP[T], RiP[T];
    #pragma unroll
    for (int i = 0; i < T; ++i) {
        float rr[2] = {0.f, 0.f}, ri[2] = {0.f, 0.f};
        #pragma unroll
        for (int j = i; j < T; ++j) {
            const float br2 = btr[j - i], bi2 = bti[j - i];
            #pragma unroll
            for (int s = 0; s < 2; ++s) {
                rr[s] += br2 * qer[T - 1 - j][s] - bi2 * qei[T - 1 - j][s];
                ri[s] += br2 * qei[T - 1 - j][s] + bi2 * qer[T - 1 - j][s];
            }
        }
        RrP[i] = pk(rr[0], rr[1]);
        RiP[i] = pk(ri[0], ri[1]);
    }

    // packed constants
    u64 UEr[T], UEi[T], CEr[T], CEi[T];
    #pragma unroll
    for (int m = 0; m < T; ++m) {
        UEr[m] = pk(uer[m][0], uer[m][1]);
        UEi[m] = pk(uei[m][0], uei[m][1]);
        CEr[m] = pk(cer[m][0], cer[m][1]);
        CEi[m] = pk(cei[m][0], cei[m][1]);
    }
    const u64 E8r = pk(e8r[0], e8r[1]);
    const u64 E8i = pk(e8i[0], e8i[1]);
    const u64 NEG1 = pk(-1.f, -1.f);

    u64 Xr = pk(xr0[0], xr0[1]);
    u64 Xi = pk(xi0[0], xi0[1]);

    float* __restrict__ o_ptr = out + (long)h * L;
    const int NB = L / T;
    const int Lb = NB * T;

    float* const sp = &s_part[wip][0];
    const float* const pairf = reinterpret_cast<const float*>(&s_pair[wip][0]);
    const float* const kapf = reinterpret_cast<const float*>(&s_kap[wip][0]);

    // rowsum row: lanes 0-23 -> rows 0-23; lanes 24-31 duplicate rows 8-15 (mui)
    const int row = (lane < 24) ? lane : (lane - 16);
    const ulonglong2* const rowp =
        reinterpret_cast<const ulonglong2*>(sp + row * ROWP);

    // dup-store: sign and target address (one STS.64 per lane, branchless)
    // lanes 0-7: murN -> s_pair[i].x ; 8-15: muiP -> s_pair[i].y ;
    // 16-23: kap -> s_kap[i] ; 24-31: muiN -> s_muiN[i]
    const float dsign = (lane < 8 || lane >= 24) ? -1.f : 1.f;
    char* dupaddr;
    {
        char* const pb = reinterpret_cast<char*>(&s_pair[wip][0]);
        char* const kb = reinterpret_cast<char*>(&s_kap[wip][0]);
        char* const nb = reinterpret_cast<char*>(&s_muiN[wip][0]);
        if (lane < 8)       dupaddr = pb + lane * 16;
        else if (lane < 16) dupaddr = pb + (lane - 8) * 16 + 8;
        else if (lane < 24) dupaddr = kb + (lane - 16) * 8;
        else                dupaddr = nb + (lane - 24) * 8;
    }

    // premasked conv coefficients: k_m = kap_m + sum_{d<m} wr_d*murN + wi_d*muiP
    const int mo = lane & 7;
    float cwr[T - 1], cwi[T - 1];
    int cix[T - 1];
    #pragma unroll
    for (int d = 0; d < T - 1; ++d) {
        const bool act = d < mo;
        const int idx = act ? (mo - 1 - d) : 0;
        cwr[d] = act ? wcr[d] : 0.f;
        cwi[d] = act ? wci[d] : 0.f;
        cix[d] = idx * 4;   // float idx of murN_i; muiP_i at +2
    }
    const bool do_store = (lane < 8);

    #pragma unroll 1
    for (int b = 0; b < NB; ++b) {
        const u64 XiN = f2mul(Xi, NEG1);

        // dots -> u64 scatter: rows m (mur), 8+m (mui), 16+m (kap)
        #pragma unroll
        for (int m = 0; m < T; ++m) {
            const u64 ar = f2fma(UEi[m], XiN, f2mul(UEr[m], Xr));
            const u64 br = f2fma(UEi[m], Xr,  f2mul(UEr[m], Xi));
            const u64 cr = f2fma(CEi[m], XiN, f2mul(CEr[m], Xr));
            *reinterpret_cast<u64*>(sp + m * ROWP + 2 * lane) = ar;
            *reinterpret_cast<u64*>(sp + (8 + m) * ROWP + 2 * lane) = br;
            *reinterpret_cast<u64*>(sp + (16 + m) * ROWP + 2 * lane) = cr;
        }
        __syncwarp();

        // packed rowsum: FULL 64-float row = 16 x LDS.128, f2add tree
        {
            u64 a0, a1, a2, a3;
            {
                const ulonglong2 v0 = rowp[0], v1 = rowp[1],
                                 v2 = rowp[2], v3 = rowp[3];
                const ulonglong2 v4 = rowp[4], v5 = rowp[5],
                                 v6 = rowp[6], v7 = rowp[7];
                a0 = f2add(f2add(v0.x, v0.y), f2add(v4.x, v4.y));
                a1 = f2add(f2add(v1.x, v1.y), f2add(v5.x, v5.y));
                a2 = f2add(f2add(v2.x, v2.y), f2add(v6.x, v6.y));
                a3 = f2add(f2add(v3.x, v3.y), f2add(v7.x, v7.y));
            }
            {
                const ulonglong2 v0 = rowp[8],  v1 = rowp[9],
                                 v2 = rowp[10], v3 = rowp[11];
                const ulonglong2 v4 = rowp[12], v5 = rowp[13],
                                 v6 = rowp[14], v7 = rowp[15];
                a0 = f2add(a0, f2add(f2add(v0.x, v0.y), f2add(v4.x, v4.y)));
                a1 = f2add(a1, f2add(f2add(v1.x, v1.y), f2add(v5.x, v5.y)));
                a2 = f2add(a2, f2add(f2add(v2.x, v2.y), f2add(v6.x, v6.y)));
                a3 = f2add(a3, f2add(f2add(v3.x, v3.y), f2add(v7.x, v7.y)));
            }
            const float2 f = up(f2add(f2add(a0, a1), f2add(a2, a3)));
            const float rs = dsign * (f.x + f.y);
            *reinterpret_cast<u64*>(dupaddr) = pk(rs, rs);
        }
        __syncwarp();

        // update: Xr' = E.Xr + sum(murN*Rr + muiP*Ri); Xi' = E.Xi + sum(murN*Ri + muiN*Rr)
        {
            u64 A0 = f2fma(E8i, XiN, f2mul(E8r, Xr));
            u64 B0 = f2fma(E8i, Xr,  f2mul(E8r, Xi));
            u64 A1 = pk(0.f, 0.f), B1 = pk(0.f, 0.f);
            const ulonglong2* const mnp =
                reinterpret_cast<const ulonglong2*>(&s_muiN[wip][0]);
            #pragma unroll
            for (int j = 0; j < 4; ++j) {
                const ulonglong2 p0 = s_pair[wip][2 * j];
                const ulonglong2 p1 = s_pair[wip][2 * j + 1];
                const ulonglong2 mn = mnp[j];
                const int i0 = 2 * j, i1 = 2 * j + 1;
                A0 = f2fma(p0.x, RrP[i0], f2fma(p0.y, RiP[i0], A0));
                B0 = f2fma(p0.x, RiP[i0], f2fma(mn.x, RrP[i0], B0));
                A1 = f2fma(p1.x, RrP[i1], f2fma(p1.y, RiP[i1], A1));
                B1 = f2fma(p1.x, RiP[i1], f2fma(mn.y, RrP[i1], B1));
            }
            Xr = f2add(A0, A1);
            Xi = f2add(B0, B1);
        }

        // outputs: kv = kap[mo] + sum_d cwr[d]*murN[idx] + cwi[d]*muiP[idx]
        {
            float kv = kapf[2 * mo];
            #pragma unroll
            for (int d = 0; d < T - 1; ++d)
                kv = fmaf(cwr[d], pairf[cix[d]], fmaf(cwi[d], pairf[cix[d] + 2], kv));
            if (do_store) o_ptr[b * T + mo] = kv;
        }
    }

    // scalar tail (L % T != 0; unused for L=2048)
    for (int l = Lb; l < L; ++l) {
        float2 xr2 = up(Xr), xi2 = up(Xi);
        float xrr[2] = {xr2.x, xr2.y}, xii[2] = {xi2.x, xi2.y};
        float sr2 = 0.f, si2 = 0.f, kv = 0.f;
        #pragma unroll
        for (int s = 0; s < 2; ++s) {
            sr2 += ur_[s] * xrr[s] - ui_[s] * xii[s];
            si2 += ur_[s] * xii[s] + ui_[s] * xrr[s];
            kv  += c2r[s] * xrr[s] - c2i[s] * xii[s];
        }
        sr2 = wsum(sr2); si2 = wsum(si2); kv = wsum(kv);
        if (lane == 0) o_ptr[l] = kv;
        float nxr[2], nxi[2];
        #pragma unroll
        for (int s = 0; s < 2; ++s) {
            nxr[s] = er[s] * xrr[s] - ei[s] * xii[s] - (sr2 * qr[s] - si2 * qi[s]);
            nxi[s] = er[s] * xii[s] + ei[s] * xrr[s] - (sr2 * qi[s] + si2 * qr[s]);
        }
        Xr = pk(nxr[0], nxr[1]); Xi = pk(nxi[0], nxi[1]);
    }
}

extern "C" void kernel_launch(void* const* d_in, const int* in_sizes, int n_in,
                              void* d_out, int out_size) {
    const float* Ar = (const float*)d_in[0];
    const float* Ai = (const float*)d_in[1];
    const float* Br = (const float*)d_in[2];
    const float* Bi = (const float*)d_in[3];
    const float* Pr = (const float*)d_in[4];
    const float* Pi = (const float*)d_in[5];
    const float* Cr = (const float*)d_in[6];
    const float* Ci = (const float*)d_in[7];
    const float* ld = (const float*)d_in[8];
    float* out = (float*)d_out;

    const int H = in_sizes[8];          // 256
    const int L = out_size / H;         // 2048

    const int blocks = (H + 1) / 2;     // 2 heads per CTA, 1 warp each
    ssm_dplr_kernel<<<blocks, 64>>>(
        Ar, Ai, Br, Bi, Pr, Pi, Cr, Ci, ld, out, H, L);
}

// round 13
// speedup vs baseline: 1.2747x; 1.2747x over previous
#include <cuda_runtime.h>

// S4/DPLR kernel materialization, H=256, N2=64, RANK=1, CH=1, L=2048.
// One warp per head (lane holds states n=lane, n=lane+32 packed as f32x2).
// T=8 blocked recurrence, linear recombination, smem-transpose reductions.
// Base = R7 (68us, 505 cyc/block). This round: (1) rank-8 update split into
// 4+4 accumulator chains (packed f32x2 ops measure long-latency; shorten the
// exposed chain), (2) conv+store deferred one block via parity-double-buffered
// s_res so it issues inside the next block's scatter->rowsum latency window.

#define T 8

typedef unsigned long long u64;

__device__ __forceinline__ float wsum(float v) {
    #pragma unroll
    for (int o = 16; o; o >>= 1) v += __shfl_xor_sync(0xffffffffu, v, o);
    return v;
}
__device__ __forceinline__ u64 pk(float x, float y) {
    u64 r; asm("mov.b64 %0,{%1,%2};" : "=l"(r) : "f"(x), "f"(y)); return r;
}
__device__ __forceinline__ float2 up(u64 a) {
    float2 v; asm("mov.b64 {%0,%1},%2;" : "=f"(v.x), "=f"(v.y) : "l"(a)); return v;
}
__device__ __forceinline__ u64 f2fma(u64 a, u64 b, u64 c) {
    u64 d; asm("fma.rn.f32x2 %0,%1,%2,%3;" : "=l"(d) : "l"(a), "l"(b), "l"(c)); return d;
}
__device__ __forceinline__ u64 f2mul(u64 a, u64 b) {
    u64 d; asm("mul.rn.f32x2 %0,%1,%2;" : "=l"(d) : "l"(a), "l"(b)); return d;
}
__device__ __forceinline__ u64 f2add(u64 a, u64 b) {
    u64 d; asm("add.rn.f32x2 %0,%1,%2;" : "=l"(d) : "l"(a), "l"(b)); return d;
}

#define ROWP 36  // padded row stride (floats): conflict-free for float4 loads

__global__ __launch_bounds__(64, 1) void ssm_dplr_kernel(
    const float* __restrict__ Ar, const float* __restrict__ Ai,
    const float* __restrict__ Br, const float* __restrict__ Bi,
    const float* __restrict__ Pr, const float* __restrict__ Pi,
    const float* __restrict__ Cr, const float* __restrict__ Ci,
    const float* __restrict__ logdt,
    float* __restrict__ out, int H, int L)
{
    __shared__ __align__(16) float s_part[2][24 * ROWP];
    __shared__ __align__(16) float s_res[2][2][32];   // [warp][parity][24 used]

    const int h = blockIdx.x * (blockDim.x >> 5) + (threadIdx.x >> 5);
    if (h >= H) return;
    const int wip = threadIdx.x >> 5;
    const int lane = threadIdx.x & 31;
    const int base = h * 64 + lane;

    const float dt  = expf(logdt[h]);
    const float del = 0.5f * dt;

    // ---- per-slot scalar setup ----
    float er[2], ei[2], qr[2], qi[2], ur_[2], ui_[2], c2r[2], c2i[2];
    float pr[2], pi[2], d_r[2], d_i[2];
    float mmr[2], mmi[2];

    float red4[4];
    red4[0] = red4[1] = red4[2] = red4[3] = 0.f;
    #pragma unroll
    for (int s = 0; s < 2; ++s) {
        const int n = base + 32 * s;
        const float lr = -Ar[n], li = -Ai[n];
        const float ar = 1.f + del * lr, ai = del * li;
        const float mr = 1.f - del * lr, mi = -del * li;
        const float idm = 1.f / (mr * mr + mi * mi);
        d_r[s] = mr * idm; d_i[s] = -mi * idm;
        pr[s] = Pr[n]; pi[s] = Pi[n];
        er[s] = d_r[s] * ar - d_i[s] * ai;  ei[s] = d_r[s] * ai + d_i[s] * ar;
        qr[s] = d_r[s] * pr[s] - d_i[s] * pi[s];
        qi[s] = d_r[s] * pi[s] + d_i[s] * pr[s];
        c2r[s] = 2.f * Cr[n]; c2i[s] = 2.f * Ci[n];
        const float pp = pr[s] * pr[s] + pi[s] * pi[s];
        red4[0] += d_r[s] * pp; red4[1] += d_i[s] * pp;
        const float zr = dt * Br[n], zi = dt * Bi[n];
        mmr[s] = d_r[s] * zr - d_i[s] * zi;
        mmi[s] = d_r[s] * zi + d_i[s] * zr;
        red4[2] += pr[s] * mmr[s] + pi[s] * mmi[s];
        red4[3] += pr[s] * mmi[s] - pi[s] * mmr[s];
    }
    #pragma unroll
    for (int o = 16; o; o >>= 1)
        #pragma unroll
        for (int k = 0; k < 4; ++k)
            red4[k] += __shfl_xor_sync(0xffffffffu, red4[k], o);

    const float wr0 = 1.f + del * red4[0], wi0 = del * red4[1];
    const float iw = 1.f / (wr0 * wr0 + wi0 * wi0);
    const float gar = del * wr0 * iw, gai = -del * wi0 * iw;
    const float dkr = del * red4[0], dki = del * red4[1];
    const float alr = del - (gar * dkr - gai * dki);
    const float ali = -(gar * dki + gai * dkr);

    #pragma unroll
    for (int s = 0; s < 2; ++s) {
        const float gr2 = pr[s] * er[s] + pi[s] * ei[s];
        const float gi2 = pr[s] * ei[s] - pi[s] * er[s];
        ur_[s] = alr * pr[s] + ali * pi[s] + gar * gr2 - gai * gi2;
        ui_[s] = -alr * pi[s] + ali * pr[s] + gar * gi2 + gai * gr2;
    }

    // initial state x = dB
    float xr0[2], xi0[2];
    {
        const float gtr = gar * red4[2] - gai * red4[3];
        const float gti = gar * red4[3] + gai * red4[2];
        #pragma unroll
        for (int s = 0; s < 2; ++s) {
            xr0[s] = mmr[s] - (gtr * qr[s] - gti * qi[s]);
            xi0[s] = mmi[s] - (gtr * qi[s] + gti * qr[s]);
        }
    }

    // ---- powers m=0..T-1 ----
    float qer[T][2], qei[T][2], uer[T][2], uei[T][2], cer[T][2], cei[T][2];
    float e8r[2], e8i[2];
    {
        float emr[2] = {1.f, 1.f}, emi[2] = {0.f, 0.f};
        #pragma unroll
        for (int m = 0; m < T; ++m) {
            #pragma unroll
            for (int s = 0; s < 2; ++s) {
                qer[m][s] = qr[s] * emr[s] - qi[s] * emi[s];
                qei[m][s] = qr[s] * emi[s] + qi[s] * emr[s];
                uer[m][s] = ur_[s] * emr[s] - ui_[s] * emi[s];
                uei[m][s] = ur_[s] * emi[s] + ui_[s] * emr[s];
                cer[m][s] = c2r[s] * emr[s] - c2i[s] * emi[s];
                cei[m][s] = c2r[s] * emi[s] + c2i[s] * emr[s];
                const float t2 = emr[s] * er[s] - emi[s] * ei[s];
                emi[s] = emr[s] * ei[s] + emi[s] * er[s];
                emr[s] = t2;
            }
        }
        e8r[0] = emr[0]; e8i[0] = emi[0]; e8r[1] = emr[1]; e8i[1] = emi[1];
    }

    // ---- nu_m, eta_m for m=0..T-2 ----
    float red[4 * (T - 1)];
    #pragma unroll
    for (int m = 0; m < T - 1; ++m) {
        float a = 0.f, b = 0.f, c = 0.f, d = 0.f;
        #pragma unroll
        for (int s = 0; s < 2; ++s) {
            a += ur_[s] * qer[m][s] - ui_[s] * qei[m][s];
            b += ur_[s] * qei[m][s] + ui_[s] * qer[m][s];
            c += c2r[s] * qer[m][s] - c2i[s] * qei[m][s];
            d += c2r[s] * qei[m][s] + c2i[s] * qer[m][s];
        }
        red[4 * m] = a; red[4 * m + 1] = b; red[4 * m + 2] = c; red[4 * m + 3] = d;
    }
    #pragma unroll
    for (int o = 16; o; o >>= 1)
        #pragma unroll
        for (int k = 0; k < 4 * (T - 1); ++k)
            red[k] += __shfl_xor_sync(0xffffffffu, red[k], o);

    float nur[T - 1], nui[T - 1], etr[T - 1], eti[T - 1];
    #pragma unroll
    for (int m = 0; m < T - 1; ++m) {
        nur[m] = red[4 * m];     nui[m] = red[4 * m + 1];
        etr[m] = red[4 * m + 2]; eti[m] = red[4 * m + 3];
    }

    // beta = (1 + z*nu)^{-1}
    float btr[T], bti[T];
    btr[0] = 1.f; bti[0] = 0.f;
    #pragma unroll
    for (int m = 1; m < T; ++m) {
        float a = 0.f, b = 0.f;
        #pragma unroll
        for (int j = 0; j < m; ++j) {
            a -= nur[m - 1 - j] * btr[j] - nui[m - 1 - j] * bti[j];
            b -= nur[m - 1 - j] * bti[j] + nui[m - 1 - j] * btr[j];
        }
        btr[m] = a; bti[m] = b;
    }
    // w = eta (*) beta
    float wcr[T - 1], wci[T - 1];
    #pragma unroll
    for (int m = 0; m < T - 1; ++m) {
        float a = 0.f, b = 0.f;
        #pragma unroll
        for (int j = 0; j <= m; ++j) {
            a += etr[j] * btr[m - j] - eti[j] * bti[m - j];
            b += etr[j] * bti[m - j] + eti[j] * btr[m - j];
        }
        wcr[m] = a; wci[m] = b;
    }

    // R_i = sum_{j>=i} beta_{j-i} E^{T-1-j} q
    float rrr[T][2], rri[T][2];
    #pragma unroll
    for (int i = 0; i < T; ++i) {
        #pragma unroll
        for (int s = 0; s < 2; ++s) { rrr[i][s] = 0.f; rri[i][s] = 0.f; }
        #pragma unroll
        for (int j = i; j < T; ++j) {
            const float br2 = btr[j - i], bi2 = bti[j - i];
            #pragma unroll
            for (int s = 0; s < 2; ++s) {
                rrr[i][s] += br2 * qer[T - 1 - j][s] - bi2 * qei[T - 1 - j][s];
                rri[i][s] += br2 * qei[T - 1 - j][s] + bi2 * qer[T - 1 - j][s];
            }
        }
    }

    // ---- pack persistent packed constants ----
    u64 UEr[T], UEi[T], CEr[T], CEi[T], Rr[T], Ri[T];
    #pragma unroll
    for (int m = 0; m < T; ++m) {
        UEr[m] = pk(uer[m][0], uer[m][1]);
        UEi[m] = pk(uei[m][0], uei[m][1]);
        CEr[m] = pk(cer[m][0], cer[m][1]);
        CEi[m] = pk(cei[m][0], cei[m][1]);
        Rr[m]  = pk(rrr[m][0], rrr[m][1]);
        Ri[m]  = pk(rri[m][0], rri[m][1]);
    }
    const u64 E8r = pk(e8r[0], e8r[1]);
    const u64 E8i = pk(e8i[0], e8i[1]);
    const u64 NEG1 = pk(-1.f, -1.f);
    const u64 ZERO = pk(0.f, 0.f);

    u64 Xr = pk(xr0[0], xr0[1]);
    u64 Xi = pk(xi0[0], xi0[1]);

    float* __restrict__ o_ptr = out + (long)h * L;
    const int NB = L / T;
    const int Lb = NB * T;

    float* const sp = &s_part[wip][0];

    // branchless row assignment: lanes 24-31 duplicate rows 0-7 (harmless)
    const int row = (lane >= 24) ? (lane - 24) : lane;
    const float4* const rowp = reinterpret_cast<const float4*>(sp + row * ROWP);

    // per-lane premasked conv coefficients (lane handles output m = lane & 7)
    const int mo = lane & 7;
    float mwr[T - 1], mwi[T - 1];
    int mix0[T - 1], mix1[T - 1];
    #pragma unroll
    for (int d = 0; d < T - 1; ++d) {
        const bool act = d < mo;
        const int idx = act ? (mo - 1 - d) : 0;
        mwr[d] = act ? -wcr[d] : 0.f;
        mwi[d] = act ? wci[d] : 0.f;
        mix0[d] = idx;
        mix1[d] = 8 + idx;
    }
    const bool do_store = (lane < 8);

    #pragma unroll 1
    for (int b = 0; b < NB; ++b) {
        const int par = b & 1;
        const u64 XiN = f2mul(Xi, NEG1);

        // dots -> scatter partials: rows m -> mur, 8+m -> mui, 16+m -> kap
        #pragma unroll
        for (int m = 0; m < T; ++m) {
            float2 a = up(f2fma(UEi[m], XiN, f2mul(UEr[m], Xr)));
            float2 b2 = up(f2fma(UEi[m], Xr,  f2mul(UEr[m], Xi)));
            float2 c = up(f2fma(CEi[m], XiN, f2mul(CEr[m], Xr)));
            sp[m * ROWP + lane]        = a.x + a.y;
            sp[(8 + m) * ROWP + lane]  = b2.x + b2.y;
            sp[(16 + m) * ROWP + lane] = c.x + c.y;
        }
        __syncwarp();

        // deferred outputs of block b-1 — fills the scatter->rowsum window
        if (b) {
            const float* const rb = &s_res[wip][par ^ 1][0];
            float kv = rb[16 + mo];
            #pragma unroll
            for (int d = 0; d < T - 1; ++d)
                kv = fmaf(mwr[d], rb[mix0[d]], fmaf(mwi[d], rb[mix1[d]], kv));
            if (do_store) o_ptr[(b - 1) * T + mo] = kv;
        }

        // all 32 lanes sum a row (lanes 24-31 duplicate rows 0-7)
        {
            float4 v0 = rowp[0], v1 = rowp[1], v2 = rowp[2], v3 = rowp[3];
            float4 v4 = rowp[4], v5 = rowp[5], v6 = rowp[6], v7 = rowp[7];
            float4 t0 = make_float4(v0.x + v4.x, v0.y + v4.y, v0.z + v4.z, v0.w + v4.w);
            float4 t1 = make_float4(v1.x + v5.x, v1.y + v5.y, v1.z + v5.z, v1.w + v5.w);
            float4 t2 = make_float4(v2.x + v6.x, v2.y + v6.y, v2.z + v6.z, v2.w + v6.w);
            float4 t3 = make_float4(v3.x + v7.x, v3.y + v7.y, v3.z + v7.z, v3.w + v7.w);
            float4 u0 = make_float4(t0.x + t2.x, t0.y + t2.y, t0.z + t2.z, t0.w + t2.w);
            float4 u1 = make_float4(t1.x + t3.x, t1.y + t3.y, t1.z + t3.z, t1.w + t3.w);
            float4 ww = make_float4(u0.x + u1.x, u0.y + u1.y, u0.z + u1.z, u0.w + u1.w);
            s_res[wip][par][lane] = (ww.x + ww.y) + (ww.z + ww.w);
        }
        __syncwarp();

        // broadcast mu (uniform-address LDS)
        const float* const rbc = &s_res[wip][par][0];
        const float4 m0 = *reinterpret_cast<const float4*>(rbc + 0);
        const float4 m1 = *reinterpret_cast<const float4*>(rbc + 4);
        const float4 n0 = *reinterpret_cast<const float4*>(rbc + 8);
        const float4 n1 = *reinterpret_cast<const float4*>(rbc + 12);
        const float mur[T] = {m0.x, m0.y, m0.z, m0.w, m1.x, m1.y, m1.z, m1.w};
        const float mui[T] = {n0.x, n0.y, n0.z, n0.w, n1.x, n1.y, n1.z, n1.w};

        // state update, FOUR accumulator chains per component (short chains)
        {
            u64 A0 = f2fma(E8i, XiN, f2mul(E8r, Xr));
            u64 B0 = f2fma(E8i, Xr,  f2mul(E8r, Xi));
            u64 A1 = ZERO, B1 = ZERO, A2 = ZERO, B2 = ZERO, A3 = ZERO, B3 = ZERO;
            #pragma unroll
            for (int i = 0; i < T; i += 4) {
                const u64 a0 = pk(-mur[i], -mur[i]);
                const u64 b0 = pk(mui[i], mui[i]);
                const u64 c0 = pk(-mui[i], -mui[i]);
                A0 = f2fma(a0, Rr[i], f2fma(b0, Ri[i], A0));
                B0 = f2fma(a0, Ri[i], f2fma(c0, Rr[i], B0));
                const u64 a1 = pk(-mur[i + 1], -mur[i + 1]);
                const u64 b1 = pk(mui[i + 1], mui[i + 1]);
                const u64 c1 = pk(-mui[i + 1], -mui[i + 1]);
                A1 = f2fma(a1, Rr[i + 1], f2fma(b1, Ri[i + 1], A1));
                B1 = f2fma(a1, Ri[i + 1], f2fma(c1, Rr[i + 1], B1));
                const u64 a2 = pk(-mur[i + 2], -mur[i + 2]);
                const u64 b2 = pk(mui[i + 2], mui[i + 2]);
                const u64 c2 = pk(-mui[i + 2], -mui[i + 2]);
                A2 = f2fma(a2, Rr[i + 2], f2fma(b2, Ri[i + 2], A2));
                B2 = f2fma(a2, Ri[i + 2], f2fma(c2, Rr[i + 2], B2));
                const u64 a3 = pk(-mur[i + 3], -mur[i + 3]);
                const u64 b3 = pk(mui[i + 3], mui[i + 3]);
                const u64 c3 = pk(-mui[i + 3], -mui[i + 3]);
                A3 = f2fma(a3, Rr[i + 3], f2fma(b3, Ri[i + 3], A3));
                B3 = f2fma(a3, Ri[i + 3], f2fma(c3, Rr[i + 3], B3));
            }
            Xr = f2add(f2add(A0, A1), f2add(A2, A3));
            Xi = f2add(f2add(B0, B1), f2add(B2, B3));
        }
    }

    // final deferred outputs (block NB-1)
    {
        const float* const rb = &s_res[wip][(NB - 1) & 1][0];
        float kv = rb[16 + mo];
        #pragma unroll
        for (int d = 0; d < T - 1; ++d)
            kv = fmaf(mwr[d], rb[mix0[d]], fmaf(mwi[d], rb[mix1[d]], kv));
        if (do_store) o_ptr[(NB - 1) * T + mo] = kv;
    }

    // scalar tail (L % T != 0; unused for L=2048)
    for (int l = Lb; l < L; ++l) {
        float2 xr2 = up(Xr), xi2 = up(Xi);
        float xrr[2] = {xr2.x, xr2.y}, xii[2] = {xi2.x, xi2.y};
        float sr2 = 0.f, si2 = 0.f, kv = 0.f;
        #pragma unroll
        for (int s = 0; s < 2; ++s) {
            sr2 += ur_[s] * xrr[s] - ui_[s] * xii[s];
            si2 += ur_[s] * xii[s] + ui_[s] * xrr[s];
            kv  += c2r[s] * xrr[s] - c2i[s] * xii[s];
        }
        sr2 = wsum(sr2); si2 = wsum(si2); kv = wsum(kv);
        if (lane == 0) o_ptr[l] = kv;
        float nxr[2], nxi[2];
        #pragma unroll
        for (int s = 0; s < 2; ++s) {
            nxr[s] = er[s] * xrr[s] - ei[s] * xii[s] - (sr2 * qr[s] - si2 * qi[s]);
            nxi[s] = er[s] * xii[s] + ei[s] * xrr[s] - (sr2 * qi[s] + si2 * qr[s]);
        }
        Xr = pk(nxr[0], nxr[1]); Xi = pk(nxi[0], nxi[1]);
    }
}

extern "C" void kernel_launch(void* const* d_in, const int* in_sizes, int n_in,
                              void* d_out, int out_size) {
    const float* Ar = (const float*)d_in[0];
    const float* Ai = (const float*)d_in[1];
    const float* Br = (const float*)d_in[2];
    const float* Bi = (const float*)d_in[3];
    const float* Pr = (const float*)d_in[4];
    const float* Pi = (const float*)d_in[5];
    const float* Cr = (const float*)d_in[6];
    const float* Ci = (const float*)d_in[7];
    const float* ld = (const float*)d_in[8];
    float* out = (float*)d_out;

    const int H = in_sizes[8];          // 256
    const int L = out_size / H;         // CH = 1 -> 2048

    const int warps_per_block = 2;
    const int blocks = (H + warps_per_block - 1) / warps_per_block;
    ssm_dplr_kernel<<<blocks, warps_per_block * 32>>>(
        Ar, Ai, Br, Bi, Pr, Pi, Cr, Ci, ld, out, H, L);
}

// round 14
// speedup vs baseline: 1.4880x; 1.1673x over previous
#include <cuda_runtime.h>

// S4/DPLR kernel materialization, H=256, N2=64, RANK=1, CH=1, L=2048.
// One warp per head (lane holds states n=lane, n=lane+32 packed as f32x2).
// T=8 blocked recurrence, linear recombination, smem-transpose reductions.
// Base = R7 (68us) with IDENTICAL ordering (scatter -> rowsum -> update ->
// conv tail). Changes: rowsum results stored as sign-baked duplicated u64
// (murN/muiP/muiN/kap) -> update multipliers load via LDS.128 with no
// pk/negate movs; conv reads the same buffer; update split into 4 chains.

#define T 8

typedef unsigned long long u64;

__device__ __forceinline__ float wsum(float v) {
    #pragma unroll
    for (int o = 16; o; o >>= 1) v += __shfl_xor_sync(0xffffffffu, v, o);
    return v;
}
__device__ __forceinline__ u64 pk(float x, float y) {
    u64 r; asm("mov.b64 %0,{%1,%2};" : "=l"(r) : "f"(x), "f"(y)); return r;
}
__device__ __forceinline__ float2 up(u64 a) {
    float2 v; asm("mov.b64 {%0,%1},%2;" : "=f"(v.x), "=f"(v.y) : "l"(a)); return v;
}
__device__ __forceinline__ u64 f2fma(u64 a, u64 b, u64 c) {
    u64 d; asm("fma.rn.f32x2 %0,%1,%2,%3;" : "=l"(d) : "l"(a), "l"(b), "l"(c)); return d;
}
__device__ __forceinline__ u64 f2mul(u64 a, u64 b) {
    u64 d; asm("mul.rn.f32x2 %0,%1,%2;" : "=l"(d) : "l"(a), "l"(b)); return d;
}
__device__ __forceinline__ u64 f2add(u64 a, u64 b) {
    u64 d; asm("add.rn.f32x2 %0,%1,%2;" : "=l"(d) : "l"(a), "l"(b)); return d;
}

#define ROWP 36  // padded row stride (floats): conflict-free for float4 loads

__global__ __launch_bounds__(64, 1) void ssm_dplr_kernel(
    const float* __restrict__ Ar, const float* __restrict__ Ai,
    const float* __restrict__ Br, const float* __restrict__ Bi,
    const float* __restrict__ Pr, const float* __restrict__ Pi,
    const float* __restrict__ Cr, const float* __restrict__ Ci,
    const float* __restrict__ logdt,
    float* __restrict__ out, int H, int L)
{
    __shared__ __align__(16) float s_part[2][24 * ROWP];
    // [0:8) murN dup, [8:16) muiP dup, [16:24) muiN dup, [24:32) kap dup
    __shared__ __align__(16) u64 s_dup[2][32];

    const int h = blockIdx.x * (blockDim.x >> 5) + (threadIdx.x >> 5);
    if (h >= H) return;
    const int wip = threadIdx.x >> 5;
    const int lane = threadIdx.x & 31;
    const int base = h * 64 + lane;

    const float dt  = expf(logdt[h]);
    const float del = 0.5f * dt;

    // ---- per-slot scalar setup ----
    float er[2], ei[2], qr[2], qi[2], ur_[2], ui_[2], c2r[2], c2i[2];
    float pr[2], pi[2], d_r[2], d_i[2];
    float mmr[2], mmi[2];

    float red4[4];
    red4[0] = red4[1] = red4[2] = red4[3] = 0.f;
    #pragma unroll
    for (int s = 0; s < 2; ++s) {
        const int n = base + 32 * s;
        const float lr = -Ar[n], li = -Ai[n];
        const float ar = 1.f + del * lr, ai = del * li;
        const float mr = 1.f - del * lr, mi = -del * li;
        const float idm = 1.f / (mr * mr + mi * mi);
        d_r[s] = mr * idm; d_i[s] = -mi * idm;
        pr[s] = Pr[n]; pi[s] = Pi[n];
        er[s] = d_r[s] * ar - d_i[s] * ai;  ei[s] = d_r[s] * ai + d_i[s] * ar;
        qr[s] = d_r[s] * pr[s] - d_i[s] * pi[s];
        qi[s] = d_r[s] * pi[s] + d_i[s] * pr[s];
        c2r[s] = 2.f * Cr[n]; c2i[s] = 2.f * Ci[n];
        const float pp = pr[s] * pr[s] + pi[s] * pi[s];
        red4[0] += d_r[s] * pp; red4[1] += d_i[s] * pp;
        const float zr = dt * Br[n], zi = dt * Bi[n];
        mmr[s] = d_r[s] * zr - d_i[s] * zi;
        mmi[s] = d_r[s] * zi + d_i[s] * zr;
        red4[2] += pr[s] * mmr[s] + pi[s] * mmi[s];
        red4[3] += pr[s] * mmi[s] - pi[s] * mmr[s];
    }
    #pragma unroll
    for (int o = 16; o; o >>= 1)
        #pragma unroll
        for (int k = 0; k < 4; ++k)
            red4[k] += __shfl_xor_sync(0xffffffffu, red4[k], o);

    const float wr0 = 1.f + del * red4[0], wi0 = del * red4[1];
    const float iw = 1.f / (wr0 * wr0 + wi0 * wi0);
    const float gar = del * wr0 * iw, gai = -del * wi0 * iw;
    const float dkr = del * red4[0], dki = del * red4[1];
    const float alr = del - (gar * dkr - gai * dki);
    const float ali = -(gar * dki + gai * dkr);

    #pragma unroll
    for (int s = 0; s < 2; ++s) {
        const float gr2 = pr[s] * er[s] + pi[s] * ei[s];
        const float gi2 = pr[s] * ei[s] - pi[s] * er[s];
        ur_[s] = alr * pr[s] + ali * pi[s] + gar * gr2 - gai * gi2;
        ui_[s] = -alr * pi[s] + ali * pr[s] + gar * gi2 + gai * gr2;
    }

    // initial state x = dB
    float xr0[2], xi0[2];
    {
        const float gtr = gar * red4[2] - gai * red4[3];
        const float gti = gar * red4[3] + gai * red4[2];
        #pragma unroll
        for (int s = 0; s < 2; ++s) {
            xr0[s] = mmr[s] - (gtr * qr[s] - gti * qi[s]);
            xi0[s] = mmi[s] - (gtr * qi[s] + gti * qr[s]);
        }
    }

    // ---- powers m=0..T-1 ----
    float qer[T][2], qei[T][2], uer[T][2], uei[T][2], cer[T][2], cei[T][2];
    float e8r[2], e8i[2];
    {
        float emr[2] = {1.f, 1.f}, emi[2] = {0.f, 0.f};
        #pragma unroll
        for (int m = 0; m < T; ++m) {
            #pragma unroll
            for (int s = 0; s < 2; ++s) {
                qer[m][s] = qr[s] * emr[s] - qi[s] * emi[s];
                qei[m][s] = qr[s] * emi[s] + qi[s] * emr[s];
                uer[m][s] = ur_[s] * emr[s] - ui_[s] * emi[s];
                uei[m][s] = ur_[s] * emi[s] + ui_[s] * emr[s];
                cer[m][s] = c2r[s] * emr[s] - c2i[s] * emi[s];
                cei[m][s] = c2r[s] * emi[s] + c2i[s] * emr[s];
                const float t2 = emr[s] * er[s] - emi[s] * ei[s];
                emi[s] = emr[s] * ei[s] + emi[s] * er[s];
                emr[s] = t2;
            }
        }
        e8r[0] = emr[0]; e8i[0] = emi[0]; e8r[1] = emr[1]; e8i[1] = emi[1];
    }

    // ---- nu_m, eta_m for m=0..T-2 ----
    float red[4 * (T - 1)];
    #pragma unroll
    for (int m = 0; m < T - 1; ++m) {
        float a = 0.f, b = 0.f, c = 0.f, d = 0.f;
        #pragma unroll
        for (int s = 0; s < 2; ++s) {
            a += ur_[s] * qer[m][s] - ui_[s] * qei[m][s];
            b += ur_[s] * qei[m][s] + ui_[s] * qer[m][s];
            c += c2r[s] * qer[m][s] - c2i[s] * qei[m][s];
            d += c2r[s] * qei[m][s] + c2i[s] * qer[m][s];
        }
        red[4 * m] = a; red[4 * m + 1] = b; red[4 * m + 2] = c; red[4 * m + 3] = d;
    }
    #pragma unroll
    for (int o = 16; o; o >>= 1)
        #pragma unroll
        for (int k = 0; k < 4 * (T - 1); ++k)
            red[k] += __shfl_xor_sync(0xffffffffu, red[k], o);

    float nur[T - 1], nui[T - 1], etr[T - 1], eti[T - 1];
    #pragma unroll
    for (int m = 0; m < T - 1; ++m) {
        nur[m] = red[4 * m];     nui[m] = red[4 * m + 1];
        etr[m] = red[4 * m + 2]; eti[m] = red[4 * m + 3];
    }

    // beta = (1 + z*nu)^{-1}
    float btr[T], bti[T];
    btr[0] = 1.f; bti[0] = 0.f;
    #pragma unroll
    for (int m = 1; m < T; ++m) {
        float a = 0.f, b = 0.f;
        #pragma unroll
        for (int j = 0; j < m; ++j) {
            a -= nur[m - 1 - j] * btr[j] - nui[m - 1 - j] * bti[j];
            b -= nur[m - 1 - j] * bti[j] + nui[m - 1 - j] * btr[j];
        }
        btr[m] = a; bti[m] = b;
    }
    // w = eta (*) beta
    float wcr[T - 1], wci[T - 1];
    #pragma unroll
    for (int m = 0; m < T - 1; ++m) {
        float a = 0.f, b = 0.f;
        #pragma unroll
        for (int j = 0; j <= m; ++j) {
            a += etr[j] * btr[m - j] - eti[j] * bti[m - j];
            b += etr[j] * bti[m - j] + eti[j] * btr[m - j];
        }
        wcr[m] = a; wci[m] = b;
    }

    // R_i = sum_{j>=i} beta_{j-i} E^{T-1-j} q
    float rrr[T][2], rri[T][2];
    #pragma unroll
    for (int i = 0; i < T; ++i) {
        #pragma unroll
        for (int s = 0; s < 2; ++s) { rrr[i][s] = 0.f; rri[i][s] = 0.f; }
        #pragma unroll
        for (int j = i; j < T; ++j) {
            const float br2 = btr[j - i], bi2 = bti[j - i];
            #pragma unroll
            for (int s = 0; s < 2; ++s) {
                rrr[i][s] += br2 * qer[T - 1 - j][s] - bi2 * qei[T - 1 - j][s];
                rri[i][s] += br2 * qei[T - 1 - j][s] + bi2 * qer[T - 1 - j][s];
            }
        }
    }

    // ---- pack persistent packed constants ----
    u64 UEr[T], UEi[T], CEr[T], CEi[T], Rr[T], Ri[T];
    #pragma unroll
    for (int m = 0; m < T; ++m) {
        UEr[m] = pk(uer[m][0], uer[m][1]);
        UEi[m] = pk(uei[m][0], uei[m][1]);
        CEr[m] = pk(cer[m][0], cer[m][1]);
        CEi[m] = pk(cei[m][0], cei[m][1]);
        Rr[m]  = pk(rrr[m][0], rrr[m][1]);
        Ri[m]  = pk(rri[m][0], rri[m][1]);
    }
    const u64 E8r = pk(e8r[0], e8r[1]);
    const u64 E8i = pk(e8i[0], e8i[1]);
    const u64 NEG1 = pk(-1.f, -1.f);
    const u64 ZERO = pk(0.f, 0.f);

    u64 Xr = pk(xr0[0], xr0[1]);
    u64 Xi = pk(xi0[0], xi0[1]);

    float* __restrict__ o_ptr = out + (long)h * L;
    const int NB = L / T;
    const int Lb = NB * T;

    float* const sp = &s_part[wip][0];
    u64* const sd = &s_dup[wip][0];
    const float* const sdf = reinterpret_cast<const float*>(sd);
    const ulonglong2* const dpair = reinterpret_cast<const ulonglong2*>(sd);

    // rowsum row: lanes 0-23 -> rows 0-23; lanes 24-31 duplicate rows 8-15 (mui)
    const int row = (lane >= 24) ? (lane - 16) : lane;
    const float4* const rowp = reinterpret_cast<const float4*>(sp + row * ROWP);

    // dup-store sign/slot (computed once):
    // lane 0-7: murN -> slot lane (-) ; 8-15: muiP -> slot lane (+) ;
    // 16-23: kap -> slot lane+8 (+) ; 24-31: muiN -> slot lane-8 (-)
    const float dsign = (lane < 8 || lane >= 24) ? -1.f : 1.f;
    const int dslot = lane + ((lane >= 16) ? ((lane < 24) ? 8 : -8) : 0);
    u64* const dupaddr = sd + dslot;

    // premasked conv coefficients: k_m = kap_m + sum_{d<m} wcr_d*murN + wci_d*muiP
    const int mo = lane & 7;
    float cwr[T - 1], cwi[T - 1];
    int cix0[T - 1], cix1[T - 1];
    #pragma unroll
    for (int d = 0; d < T - 1; ++d) {
        const bool act = d < mo;
        const int idx = act ? (mo - 1 - d) : 0;
        cwr[d] = act ? wcr[d] : 0.f;
        cwi[d] = act ? wci[d] : 0.f;
        cix0[d] = 2 * idx;            // murN_i low float
        cix1[d] = 2 * (8 + idx);      // muiP_i low float
    }
    const bool do_store = (lane < 8);
    const int kapf0 = 2 * (24 + mo);  // kap_m low float

    #pragma unroll 1
    for (int b = 0; b < NB; ++b) {
        const u64 XiN = f2mul(Xi, NEG1);

        // dots -> scatter partials: rows m -> mur, 8+m -> mui, 16+m -> kap
        #pragma unroll
        for (int m = 0; m < T; ++m) {
            float2 a = up(f2fma(UEi[m], XiN, f2mul(UEr[m], Xr)));
            float2 b2 = up(f2fma(UEi[m], Xr,  f2mul(UEr[m], Xi)));
            float2 c = up(f2fma(CEi[m], XiN, f2mul(CEr[m], Xr)));
            sp[m * ROWP + lane]        = a.x + a.y;
            sp[(8 + m) * ROWP + lane]  = b2.x + b2.y;
            sp[(16 + m) * ROWP + lane] = c.x + c.y;
        }
        __syncwarp();

        // all 32 lanes sum a row (lanes 24-31 duplicate mui rows 8-15)
        {
            float4 v0 = rowp[0], v1 = rowp[1], v2 = rowp[2], v3 = rowp[3];
            float4 v4 = rowp[4], v5 = rowp[5], v6 = rowp[6], v7 = rowp[7];
            float4 t0 = make_float4(v0.x + v4.x, v0.y + v4.y, v0.z + v4.z, v0.w + v4.w);
            float4 t1 = make_float4(v1.x + v5.x, v1.y + v5.y, v1.z + v5.z, v1.w + v5.w);
            float4 t2 = make_float4(v2.x + v6.x, v2.y + v6.y, v2.z + v6.z, v2.w + v6.w);
            float4 t3 = make_float4(v3.x + v7.x, v3.y + v7.y, v3.z + v7.z, v3.w + v7.w);
            float4 u0 = make_float4(t0.x + t2.x, t0.y + t2.y, t0.z + t2.z, t0.w + t2.w);
            float4 u1 = make_float4(t1.x + t3.x, t1.y + t3.y, t1.z + t3.z, t1.w + t3.w);
            float4 ww = make_float4(u0.x + u1.x, u0.y + u1.y, u0.z + u1.z, u0.w + u1.w);
            const float rs = dsign * ((ww.x + ww.y) + (ww.z + ww.w));
            *dupaddr = pk(rs, rs);
        }
        __syncwarp();

        // state update, FOUR accumulator chains, multipliers via LDS.128
        // Xr' = E.Xr + sum(murN*Rr + muiP*Ri); Xi' = E.Xi + sum(murN*Ri + muiN*Rr)
        {
            u64 A0 = f2fma(E8i, XiN, f2mul(E8r, Xr));
            u64 B0 = f2fma(E8i, Xr,  f2mul(E8r, Xi));
            u64 A1 = ZERO, B1 = ZERO, A2 = ZERO, B2 = ZERO, A3 = ZERO, B3 = ZERO;
            #pragma unroll
            for (int j = 0; j < 2; ++j) {
                const ulonglong2 mrA = dpair[2 * j];        // murN 2j, 2j+1
                const ulonglong2 mrB = dpair[2 * j + 1];    // murN 2j+2, 2j+3... no:
                // dpair[0]=(murN0,murN1) dpair[1]=(murN2,murN3) ...
                const ulonglong2 mpA = dpair[4 + 2 * j];    // muiP
                const ulonglong2 mpB = dpair[4 + 2 * j + 1];
                const ulonglong2 mnA = dpair[8 + 2 * j];    // muiN
                const ulonglong2 mnB = dpair[8 + 2 * j + 1];
                const int i0 = 4 * j, i1 = 4 * j + 1, i2 = 4 * j + 2, i3 = 4 * j + 3;
                A0 = f2fma(mrA.x, Rr[i0], f2fma(mpA.x, Ri[i0], A0));
                B0 = f2fma(mrA.x, Ri[i0], f2fma(mnA.x, Rr[i0], B0));
                A1 = f2fma(mrA.y, Rr[i1], f2fma(mpA.y, Ri[i1], A1));
                B1 = f2fma(mrA.y, Ri[i1], f2fma(mnA.y, Rr[i1], B1));
                A2 = f2fma(mrB.x, Rr[i2], f2fma(mpB.x, Ri[i2], A2));
                B2 = f2fma(mrB.x, Ri[i2], f2fma(mnB.x, Rr[i2], B2));
                A3 = f2fma(mrB.y, Rr[i3], f2fma(mpB.y, Ri[i3], A3));
                B3 = f2fma(mrB.y, Ri[i3], f2fma(mnB.y, Rr[i3], B3));
            }
            Xr = f2add(f2add(A0, A1), f2add(A2, A3));
            Xi = f2add(f2add(B0, B1), f2add(B2, B3));
        }

        // outputs at tail (R7 position): kv = kap[mo] + sum cwr*murN + cwi*muiP
        {
            float kv = sdf[kapf0];
            #pragma unroll
            for (int d = 0; d < T - 1; ++d)
                kv = fmaf(cwr[d], sdf[cix0[d]], fmaf(cwi[d], sdf[cix1[d]], kv));
            if (do_store) o_ptr[b * T + mo] = kv;
        }
    }

    // scalar tail (L % T != 0; unused for L=2048)
    for (int l = Lb; l < L; ++l) {
        float2 xr2 = up(Xr), xi2 = up(Xi);
        float xrr[2] = {xr2.x, xr2.y}, xii[2] = {xi2.x, xi2.y};
        float sr2 = 0.f, si2 = 0.f, kv = 0.f;
        #pragma unroll
        for (int s = 0; s < 2; ++s) {
            sr2 += ur_[s] * xrr[s] - ui_[s] * xii[s];
            si2 += ur_[s] * xii[s] + ui_[s] * xrr[s];
            kv  += c2r[s] * xrr[s] - c2i[s] * xii[s];
        }
        sr2 = wsum(sr2); si2 = wsum(si2); kv = wsum(kv);
        if (lane == 0) o_ptr[l] = kv;
        float nxr[2], nxi[2];
        #pragma unroll
        for (int s = 0; s < 2; ++s) {
            nxr[s] = er[s] * xrr[s] - ei[s] * xii[s] - (sr2 * qr[s] - si2 * qi[s]);
            nxi[s] = er[s] * xii[s] + ei[s] * xrr[s] - (sr2 * qi[s] + si2 * qr[s]);
        }
        Xr = pk(nxr[0], nxr[1]); Xi = pk(nxi[0], nxi[1]);
    }
}

extern "C" void kernel_launch(void* const* d_in, const int* in_sizes, int n_in,
                              void* d_out, int out_size) {
    const float* Ar = (const float*)d_in[0];
    const float* Ai = (const float*)d_in[1];
    const float* Br = (const float*)d_in[2];
    const float* Bi = (const float*)d_in[3];
    const float* Pr = (const float*)d_in[4];
    const float* Pi = (const float*)d_in[5];
    const float* Cr = (const float*)d_in[6];
    const float* Ci = (const float*)d_in[7];
    const float* ld = (const float*)d_in[8];
    float* out = (float*)d_out;

    const int H = in_sizes[8];          // 256
    const int L = out_size / H;         // CH = 1 -> 2048

    const int warps_per_block = 2;
    const int blocks = (H + warps_per_block - 1) / warps_per_block;
    ssm_dplr_kernel<<<blocks, warps_per_block * 32>>>(
        Ar, Ai, Br, Bi, Pr, Pi, Cr, Ci, ld, out, H, L);
}

// round 15
// speedup vs baseline: 1.5530x; 1.0437x over previous
#include <cuda_runtime.h>

// S4/DPLR kernel materialization, H=256, N2=64, RANK=1, CH=1, L=2048.
// One warp per head (lane holds states n=lane, n=lane+32 packed as f32x2).
// T=8 blocked recurrence, linear recombination, smem-transpose reductions.
// EXACT R7 (68us) stage structure. Only changes: (1) rank-8 update split
// into FOUR accumulator chains (depth 9 -> 5) to cut exposed packed-fma
// latency; (2) negation-free R constants (RrN, Ri, RiN in registers) so
// multipliers are plain pk(mur),pk(mui) with no negate movs.

#define T 8

typedef unsigned long long u64;

__device__ __forceinline__ float wsum(float v) {
    #pragma unroll
    for (int o = 16; o; o >>= 1) v += __shfl_xor_sync(0xffffffffu, v, o);
    return v;
}
__device__ __forceinline__ u64 pk(float x, float y) {
    u64 r; asm("mov.b64 %0,{%1,%2};" : "=l"(r) : "f"(x), "f"(y)); return r;
}
__device__ __forceinline__ float2 up(u64 a) {
    float2 v; asm("mov.b64 {%0,%1},%2;" : "=f"(v.x), "=f"(v.y) : "l"(a)); return v;
}
__device__ __forceinline__ u64 f2fma(u64 a, u64 b, u64 c) {
    u64 d; asm("fma.rn.f32x2 %0,%1,%2,%3;" : "=l"(d) : "l"(a), "l"(b), "l"(c)); return d;
}
__device__ __forceinline__ u64 f2mul(u64 a, u64 b) {
    u64 d; asm("mul.rn.f32x2 %0,%1,%2;" : "=l"(d) : "l"(a), "l"(b)); return d;
}
__device__ __forceinline__ u64 f2add(u64 a, u64 b) {
    u64 d; asm("add.rn.f32x2 %0,%1,%2;" : "=l"(d) : "l"(a), "l"(b)); return d;
}

#define ROWP 36  // padded row stride (floats): conflict-free for float4 loads

__global__ __launch_bounds__(64, 1) void ssm_dplr_kernel(
    const float* __restrict__ Ar, const float* __restrict__ Ai,
    const float* __restrict__ Br, const float* __restrict__ Bi,
    const float* __restrict__ Pr, const float* __restrict__ Pi,
    const float* __restrict__ Cr, const float* __restrict__ Ci,
    const float* __restrict__ logdt,
    float* __restrict__ out, int H, int L)
{
    __shared__ __align__(16) float s_part[2][24 * ROWP];
    __shared__ __align__(16) float s_res[2][32];

    const int h = blockIdx.x * (blockDim.x >> 5) + (threadIdx.x >> 5);
    if (h >= H) return;
    const int wip = threadIdx.x >> 5;
    const int lane = threadIdx.x & 31;
    const int base = h * 64 + lane;

    const float dt  = expf(logdt[h]);
    const float del = 0.5f * dt;

    // ---- per-slot scalar setup ----
    float er[2], ei[2], qr[2], qi[2], ur_[2], ui_[2], c2r[2], c2i[2];
    float pr[2], pi[2], d_r[2], d_i[2];
    float mmr[2], mmi[2];

    float red4[4];
    red4[0] = red4[1] = red4[2] = red4[3] = 0.f;
    #pragma unroll
    for (int s = 0; s < 2; ++s) {
        const int n = base + 32 * s;
        const float lr = -Ar[n], li = -Ai[n];
        const float ar = 1.f + del * lr, ai = del * li;
        const float mr = 1.f - del * lr, mi = -del * li;
        const float idm = 1.f / (mr * mr + mi * mi);
        d_r[s] = mr * idm; d_i[s] = -mi * idm;
        pr[s] = Pr[n]; pi[s] = Pi[n];
        er[s] = d_r[s] * ar - d_i[s] * ai;  ei[s] = d_r[s] * ai + d_i[s] * ar;
        qr[s] = d_r[s] * pr[s] - d_i[s] * pi[s];
        qi[s] = d_r[s] * pi[s] + d_i[s] * pr[s];
        c2r[s] = 2.f * Cr[n]; c2i[s] = 2.f * Ci[n];
        const float pp = pr[s] * pr[s] + pi[s] * pi[s];
        red4[0] += d_r[s] * pp; red4[1] += d_i[s] * pp;
        const float zr = dt * Br[n], zi = dt * Bi[n];
        mmr[s] = d_r[s] * zr - d_i[s] * zi;
        mmi[s] = d_r[s] * zi + d_i[s] * zr;
        red4[2] += pr[s] * mmr[s] + pi[s] * mmi[s];
        red4[3] += pr[s] * mmi[s] - pi[s] * mmr[s];
    }
    #pragma unroll
    for (int o = 16; o; o >>= 1)
        #pragma unroll
        for (int k = 0; k < 4; ++k)
            red4[k] += __shfl_xor_sync(0xffffffffu, red4[k], o);

    const float wr0 = 1.f + del * red4[0], wi0 = del * red4[1];
    const float iw = 1.f / (wr0 * wr0 + wi0 * wi0);
    const float gar = del * wr0 * iw, gai = -del * wi0 * iw;
    const float dkr = del * red4[0], dki = del * red4[1];
    const float alr = del - (gar * dkr - gai * dki);
    const float ali = -(gar * dki + gai * dkr);

    #pragma unroll
    for (int s = 0; s < 2; ++s) {
        const float gr2 = pr[s] * er[s] + pi[s] * ei[s];
        const float gi2 = pr[s] * ei[s] - pi[s] * er[s];
        ur_[s] = alr * pr[s] + ali * pi[s] + gar * gr2 - gai * gi2;
        ui_[s] = -alr * pi[s] + ali * pr[s] + gar * gi2 + gai * gr2;
    }

    // initial state x = dB
    float xr0[2], xi0[2];
    {
        const float gtr = gar * red4[2] - gai * red4[3];
        const float gti = gar * red4[3] + gai * red4[2];
        #pragma unroll
        for (int s = 0; s < 2; ++s) {
            xr0[s] = mmr[s] - (gtr * qr[s] - gti * qi[s]);
            xi0[s] = mmi[s] - (gtr * qi[s] + gti * qr[s]);
        }
    }

    // ---- powers m=0..T-1 ----
    float qer[T][2], qei[T][2], uer[T][2], uei[T][2], cer[T][2], cei[T][2];
    float e8r[2], e8i[2];
    {
        float emr[2] = {1.f, 1.f}, emi[2] = {0.f, 0.f};
        #pragma unroll
        for (int m = 0; m < T; ++m) {
            #pragma unroll
            for (int s = 0; s < 2; ++s) {
                qer[m][s] = qr[s] * emr[s] - qi[s] * emi[s];
                qei[m][s] = qr[s] * emi[s] + qi[s] * emr[s];
                uer[m][s] = ur_[s] * emr[s] - ui_[s] * emi[s];
                uei[m][s] = ur_[s] * emi[s] + ui_[s] * emr[s];
                cer[m][s] = c2r[s] * emr[s] - c2i[s] * emi[s];
                cei[m][s] = c2r[s] * emi[s] + c2i[s] * emr[s];
                const float t2 = emr[s] * er[s] - emi[s] * ei[s];
                emi[s] = emr[s] * ei[s] + emi[s] * er[s];
                emr[s] = t2;
            }
        }
        e8r[0] = emr[0]; e8i[0] = emi[0]; e8r[1] = emr[1]; e8i[1] = emi[1];
    }

    // ---- nu_m, eta_m for m=0..T-2 ----
    float red[4 * (T - 1)];
    #pragma unroll
    for (int m = 0; m < T - 1; ++m) {
        float a = 0.f, b = 0.f, c = 0.f, d = 0.f;
        #pragma unroll
        for (int s = 0; s < 2; ++s) {
            a += ur_[s] * qer[m][s] - ui_[s] * qei[m][s];
            b += ur_[s] * qei[m][s] + ui_[s] * qer[m][s];
            c += c2r[s] * qer[m][s] - c2i[s] * qei[m][s];
            d += c2r[s] * qei[m][s] + c2i[s] * qer[m][s];
        }
        red[4 * m] = a; red[4 * m + 1] = b; red[4 * m + 2] = c; red[4 * m + 3] = d;
    }
    #pragma unroll
    for (int o = 16; o; o >>= 1)
        #pragma unroll
        for (int k = 0; k < 4 * (T - 1); ++k)
            red[k] += __shfl_xor_sync(0xffffffffu, red[k], o);

    float nur[T - 1], nui[T - 1], etr[T - 1], eti[T - 1];
    #pragma unroll
    for (int m = 0; m < T - 1; ++m) {
        nur[m] = red[4 * m];     nui[m] = red[4 * m + 1];
        etr[m] = red[4 * m + 2]; eti[m] = red[4 * m + 3];
    }

    // beta = (1 + z*nu)^{-1}
    float btr[T], bti[T];
    btr[0] = 1.f; bti[0] = 0.f;
    #pragma unroll
    for (int m = 1; m < T; ++m) {
        float a = 0.f, b = 0.f;
        #pragma unroll
        for (int j = 0; j < m; ++j) {
            a -= nur[m - 1 - j] * btr[j] - nui[m - 1 - j] * bti[j];
            b -= nur[m - 1 - j] * bti[j] + nui[m - 1 - j] * btr[j];
        }
        btr[m] = a; bti[m] = b;
    }
    // w = eta (*) beta
    float wcr[T - 1], wci[T - 1];
    #pragma unroll
    for (int m = 0; m < T - 1; ++m) {
        float a = 0.f, b = 0.f;
        #pragma unroll
        for (int j = 0; j <= m; ++j) {
            a += etr[j] * btr[m - j] - eti[j] * bti[m - j];
            b += etr[j] * bti[m - j] + eti[j] * btr[m - j];
        }
        wcr[m] = a; wci[m] = b;
    }

    // R_i = sum_{j>=i} beta_{j-i} E^{T-1-j} q
    float rrr[T][2], rri[T][2];
    #pragma unroll
    for (int i = 0; i < T; ++i) {
        #pragma unroll
        for (int s = 0; s < 2; ++s) { rrr[i][s] = 0.f; rri[i][s] = 0.f; }
        #pragma unroll
        for (int j = i; j < T; ++j) {
            const float br2 = btr[j - i], bi2 = bti[j - i];
            #pragma unroll
            for (int s = 0; s < 2; ++s) {
                rrr[i][s] += br2 * qer[T - 1 - j][s] - bi2 * qei[T - 1 - j][s];
                rri[i][s] += br2 * qei[T - 1 - j][s] + bi2 * qer[T - 1 - j][s];
            }
        }
    }

    // ---- pack persistent packed constants (negation-free update set) ----
    u64 UEr[T], UEi[T], CEr[T], CEi[T], RrN[T], RiP[T], RiN[T];
    #pragma unroll
    for (int m = 0; m < T; ++m) {
        UEr[m] = pk(uer[m][0], uer[m][1]);
        UEi[m] = pk(uei[m][0], uei[m][1]);
        CEr[m] = pk(cer[m][0], cer[m][1]);
        CEi[m] = pk(cei[m][0], cei[m][1]);
        RrN[m] = pk(-rrr[m][0], -rrr[m][1]);
        RiP[m] = pk(rri[m][0], rri[m][1]);
        RiN[m] = pk(-rri[m][0], -rri[m][1]);
    }
    const u64 E8r = pk(e8r[0], e8r[1]);
    const u64 E8i = pk(e8i[0], e8i[1]);
    const u64 NEG1 = pk(-1.f, -1.f);
    const u64 ZERO = pk(0.f, 0.f);

    u64 Xr = pk(xr0[0], xr0[1]);
    u64 Xi = pk(xi0[0], xi0[1]);

    float* __restrict__ o_ptr = out + (long)h * L;
    const int NB = L / T;
    const int Lb = NB * T;

    float* const sp = &s_part[wip][0];
    float* const sr_ = &s_res[wip][0];

    // branchless row assignment: lanes 24-31 duplicate rows 0-7 (harmless)
    const int row = (lane >= 24) ? (lane - 24) : lane;
    const float4* const rowp = reinterpret_cast<const float4*>(sp + row * ROWP);

    // per-lane premasked conv coefficients (lane handles output m = lane & 7)
    const int mo = lane & 7;
    float mwr[T - 1], mwi[T - 1];
    int mix0[T - 1], mix1[T - 1];
    #pragma unroll
    for (int d = 0; d < T - 1; ++d) {
        const bool act = d < mo;
        const int idx = act ? (mo - 1 - d) : 0;
        mwr[d] = act ? -wcr[d] : 0.f;
        mwi[d] = act ? wci[d] : 0.f;
        mix0[d] = idx;
        mix1[d] = 8 + idx;
    }
    const bool do_store = (lane < 8);

    #pragma unroll 1
    for (int b = 0; b < NB; ++b) {
        const u64 XiN = f2mul(Xi, NEG1);

        // dots -> scatter partials: rows m -> mur, 8+m -> mui, 16+m -> kap
        #pragma unroll
        for (int m = 0; m < T; ++m) {
            float2 a = up(f2fma(UEi[m], XiN, f2mul(UEr[m], Xr)));
            float2 b2 = up(f2fma(UEi[m], Xr,  f2mul(UEr[m], Xi)));
            float2 c = up(f2fma(CEi[m], XiN, f2mul(CEr[m], Xr)));
            sp[m * ROWP + lane]        = a.x + a.y;
            sp[(8 + m) * ROWP + lane]  = b2.x + b2.y;
            sp[(16 + m) * ROWP + lane] = c.x + c.y;
        }
        __syncwarp();

        // all 32 lanes sum a row (lanes 24-31 duplicate rows 0-7)
        {
            float4 v0 = rowp[0], v1 = rowp[1], v2 = rowp[2], v3 = rowp[3];
            float4 v4 = rowp[4], v5 = rowp[5], v6 = rowp[6], v7 = rowp[7];
            float4 t0 = make_float4(v0.x + v4.x, v0.y + v4.y, v0.z + v4.z, v0.w + v4.w);
            float4 t1 = make_float4(v1.x + v5.x, v1.y + v5.y, v1.z + v5.z, v1.w + v5.w);
            float4 t2 = make_float4(v2.x + v6.x, v2.y + v6.y, v2.z + v6.z, v2.w + v6.w);
            float4 t3 = make_float4(v3.x + v7.x, v3.y + v7.y, v3.z + v7.z, v3.w + v7.w);
            float4 u0 = make_float4(t0.x + t2.x, t0.y + t2.y, t0.z + t2.z, t0.w + t2.w);
            float4 u1 = make_float4(t1.x + t3.x, t1.y + t3.y, t1.z + t3.z, t1.w + t3.w);
            float4 ww = make_float4(u0.x + u1.x, u0.y + u1.y, u0.z + u1.z, u0.w + u1.w);
            sr_[lane] = (ww.x + ww.y) + (ww.z + ww.w);
        }
        __syncwarp();

        // broadcast mu (uniform-address LDS)
        const float4 m0 = *reinterpret_cast<const float4*>(sr_ + 0);
        const float4 m1 = *reinterpret_cast<const float4*>(sr_ + 4);
        const float4 n0 = *reinterpret_cast<const float4*>(sr_ + 8);
        const float4 n1 = *reinterpret_cast<const float4*>(sr_ + 12);
        const float mur[T] = {m0.x, m0.y, m0.z, m0.w, m1.x, m1.y, m1.z, m1.w};
        const float mui[T] = {n0.x, n0.y, n0.z, n0.w, n1.x, n1.y, n1.z, n1.w};

        // state update: FOUR accumulator chains, negation-free multipliers
        // Xr' = E.Xr + sum(mur*RrN + mui*RiP); Xi' = E.Xi + sum(mur*RiN + mui*RrN)
        {
            u64 A0 = f2fma(E8i, XiN, f2mul(E8r, Xr));
            u64 B0 = f2fma(E8i, Xr,  f2mul(E8r, Xi));
            u64 A1 = ZERO, B1 = ZERO, A2 = ZERO, B2 = ZERO, A3 = ZERO, B3 = ZERO;
            #pragma unroll
            for (int i = 0; i < T; i += 4) {
                const u64 r0 = pk(mur[i], mur[i]);
                const u64 s0 = pk(mui[i], mui[i]);
                A0 = f2fma(r0, RrN[i], f2fma(s0, RiP[i], A0));
                B0 = f2fma(r0, RiN[i], f2fma(s0, RrN[i], B0));
                const u64 r1 = pk(mur[i + 1], mur[i + 1]);
                const u64 s1 = pk(mui[i + 1], mui[i + 1]);
                A1 = f2fma(r1, RrN[i + 1], f2fma(s1, RiP[i + 1], A1));
                B1 = f2fma(r1, RiN[i + 1], f2fma(s1, RrN[i + 1], B1));
                const u64 r2 = pk(mur[i + 2], mur[i + 2]);
                const u64 s2 = pk(mui[i + 2], mui[i + 2]);
                A2 = f2fma(r2, RrN[i + 2], f2fma(s2, RiP[i + 2], A2));
                B2 = f2fma(r2, RiN[i + 2], f2fma(s2, RrN[i + 2], B2));
                const u64 r3 = pk(mur[i + 3], mur[i + 3]);
                const u64 s3 = pk(mui[i + 3], mui[i + 3]);
                A3 = f2fma(r3, RrN[i + 3], f2fma(s3, RiP[i + 3], A3));
                B3 = f2fma(r3, RiN[i + 3], f2fma(s3, RrN[i + 3], B3));
            }
            Xr = f2add(f2add(A0, A1), f2add(A2, A3));
            Xi = f2add(f2add(B0, B1), f2add(B2, B3));
        }

        // outputs: branchless masked conv, predicated store (R7 tail position)
        {
            float kv = sr_[16 + mo];
            #pragma unroll
            for (int d = 0; d < T - 1; ++d)
                kv = fmaf(mwr[d], sr_[mix0[d]], fmaf(mwi[d], sr_[mix1[d]], kv));
            if (do_store) o_ptr[b * T + mo] = kv;
        }
    }

    // scalar tail (L % T != 0; unused for L=2048)
    for (int l = Lb; l < L; ++l) {
        float2 xr2 = up(Xr), xi2 = up(Xi);
        float xrr[2] = {xr2.x, xr2.y}, xii[2] = {xi2.x, xi2.y};
        float sr2 = 0.f, si2 = 0.f, kv = 0.f;
        #pragma unroll
        for (int s = 0; s < 2; ++s) {
            sr2 += ur_[s] * xrr[s] - ui_[s] * xii[s];
            si2 += ur_[s] * xii[s] + ui_[s] * xrr[s];
            kv  += c2r[s] * xrr[s] - c2i[s] * xii[s];
        }
        sr2 = wsum(sr2); si2 = wsum(si2); kv = wsum(kv);
        if (lane == 0) o_ptr[l] = kv;
        float nxr[2], nxi[2];
        #pragma unroll
        for (int s = 0; s < 2; ++s) {
            nxr[s] = er[s] * xrr[s] - ei[s] * xii[s] - (sr2 * qr[s] - si2 * qi[s]);
            nxi[s] = er[s] * xii[s] + ei[s] * xrr[s] - (sr2 * qi[s] + si2 * qr[s]);
        }
        Xr = pk(nxr[0], nxr[1]); Xi = pk(nxi[0], nxi[1]);
    }
}

extern "C" void kernel_launch(void* const* d_in, const int* in_sizes, int n_in,
                              void* d_out, int out_size) {
    const float* Ar = (const float*)d_in[0];
    const float* Ai = (const float*)d_in[1];
    const float* Br = (const float*)d_in[2];
    const float* Bi = (const float*)d_in[3];
    const float* Pr = (const float*)d_in[4];
    const float* Pi = (const float*)d_in[5];
    const float* Cr = (const float*)d_in[6];
    const float* Ci = (const float*)d_in[7];
    const float* ld = (const float*)d_in[8];
    float* out = (float*)d_out;

    const int H = in_sizes[8];          // 256
    const int L = out_size / H;         // CH = 1 -> 2048

    const int warps_per_block = 2;
    const int blocks = (H + warps_per_block - 1) / warps_per_block;
    ssm_dplr_kernel<<<blocks, warps_per_block * 32>>>(
        Ar, Ai, Br, Bi, Pr, Pi, Cr, Ci, ld, out, H, L);
}